// round 12
// baseline (speedup 1.0000x reference)
#include <cuda_runtime.h>
#include <cuda_bf16.h>
#include <math.h>

#define ED 1536
#define BN 64
#define MT 64
#define NTH 256
#define NCH 12            // 12 chunks of 128

// ---- smem byte offsets (from 1KB-aligned base) ----
#define O_XB(b)  ((b) * 16384)            // X 128-chunk bf16 (two 8KB subs), double buffer
#define O_WB(b)  (32768 + (b) * 16384)    // W 128-chunk bf16 (two 8KB subs), double buffer
#define O_HH     65536                    // H bf16: 64 rows x 128B
#define O_BU     73728
#define O_S1     79872
#define O_S2     80128
#define O_MS     80384
#define O_RS     80640
#define O_NRM    80896                    // 64 x 5 fp32
#define O_INV    82176
#define SMEM_REQ (82432 + 1024)

__device__ __nv_bfloat16 g_wdh[BN * ED];   // [24][64 n][64 k]  (gamma-folded, bf16)
__device__ __nv_bfloat16 g_wuh[ED * BN];   // [24][64 d][64 k]
__device__ float g_S1[BN], g_S2[BN];

// 128B rows, 8 units of 16B, XOR swizzle
__device__ __forceinline__ unsigned SWB(unsigned r, unsigned u) {
    return r * 128 + (((u ^ r) & 7) * 16);
}

__device__ __forceinline__ void ldsm4(unsigned* r, unsigned a) {
    asm volatile("ldmatrix.sync.aligned.m8n8.x4.shared.b16 {%0,%1,%2,%3}, [%4];"
                 : "=r"(r[0]), "=r"(r[1]), "=r"(r[2]), "=r"(r[3]) : "r"(a));
}
__device__ __forceinline__ void mma_bf(float* c, const unsigned* a, const unsigned* b) {
    asm volatile("mma.sync.aligned.m16n8k16.row.col.f32.bf16.bf16.f32 "
                 "{%0,%1,%2,%3},{%4,%5,%6,%7},{%8,%9},{%0,%1,%2,%3};"
                 : "+f"(c[0]), "+f"(c[1]), "+f"(c[2]), "+f"(c[3])
                 : "r"(a[0]), "r"(a[1]), "r"(a[2]), "r"(a[3]), "r"(b[0]), "r"(b[1]));
}
__device__ __forceinline__ void cp16(unsigned dst, const void* src) {
    asm volatile("cp.async.cg.shared.global [%0], [%1], 16;" :: "r"(dst), "l"(src));
}
#define CP_COMMIT() asm volatile("cp.async.commit_group;" ::: "memory")
#define CP_WAIT0()  asm volatile("cp.async.wait_group 0;" ::: "memory")

__device__ __forceinline__ unsigned pack_bf(float a, float b) {
    __nv_bfloat16 ha = __float2bfloat16_rn(a), hb = __float2bfloat16_rn(b);
    return (unsigned)__bfloat16_as_ushort(ha) | ((unsigned)__bfloat16_as_ushort(hb) << 16);
}
__device__ __forceinline__ float gelu_exact(float t) {
    return 0.5f * t * (1.f + erff(t * 0.70710678118654752f));
}

// ---------- merged prep: blocks 0..63 -> w_down row; 64..87 -> w_up chunk ----------
__global__ void prep_all(const float* __restrict__ w_down, const float* __restrict__ b_down,
                         const float* __restrict__ gamma,  const float* __restrict__ beta,
                         const float* __restrict__ w_up) {
    int tid = threadIdx.x;
    if (blockIdx.x < 64) {
        int b = blockIdx.x;
        float s1 = 0.f, s2 = 0.f;
        for (int k = tid; k < ED; k += 256) {
            float w = w_down[b * ED + k];
            float wg = w * gamma[k];
            __nv_bfloat16 hi = __float2bfloat16_rn(wg);
            s1 += __bfloat162float(hi);        // S1 matches the bf16 weights actually used
            s2 += beta[k] * w;
            int idx = (k >> 6) * 4096 + b * 64 + (k & 63);
            g_wdh[idx] = hi;
        }
        __shared__ float r1[256], r2[256];
        r1[tid] = s1; r2[tid] = s2; __syncthreads();
        for (int s = 128; s > 0; s >>= 1) {
            if (tid < s) { r1[tid] += r1[tid + s]; r2[tid] += r2[tid + s]; }
            __syncthreads();
        }
        if (tid == 0) { g_S1[b] = r1[0]; g_S2[b] = r2[0] + b_down[b]; }
    } else {
        int c = blockIdx.x - 64;
        for (int i = tid; i < 4096; i += 256) {
            int d = i >> 6, k = i & 63;
            g_wuh[c * 4096 + i] = __float2bfloat16_rn(w_up[(c * 64 + d) * BN + k]);
        }
    }
}

// stage one 16KB (128-wide) weight chunk: two consecutive 4096-elem sub-chunks
__device__ __forceinline__ void stage_w128(unsigned dst_base, const __nv_bfloat16* src_base,
                                           int chunk128, int tid) {
    #pragma unroll
    for (int s = 0; s < 4; ++s) {
        int i = tid * 4 + s;              // 0..1023 16B units
        int sub = i >> 9;                 // 0/1
        int j = i & 511;
        int n = j >> 3, u = j & 7;
        cp16(dst_base + sub * 8192 + SWB(n, u),
             src_base + (2 * chunk128 + sub) * 4096 + n * 64 + u * 8);
    }
}

// ---------- main ----------
__global__ void __launch_bounds__(NTH, 2)
peft_mma(const float* __restrict__ x, const float* __restrict__ bup, float* __restrict__ out) {
    extern __shared__ char smraw[];
    unsigned rawa = (unsigned)__cvta_generic_to_shared(smraw);
    unsigned sa = (rawa + 1023) & ~1023u;
    char* sb = smraw + (sa - rawa);

    const int tid = threadIdx.x, warp = tid >> 5, lane = tid & 31;
    const int m = warp & 3, nh = warp >> 2;   // GEMM1: 4 m-tiles x 2 n-halves
    const long row0 = (long)blockIdx.x * MT;
    const int cr = tid >> 2, cs = tid & 3;    // conversion row / quarter
    const int cb = (lane & 3) * 2;            // col pair base

    float* BU  = (float*)(sb + O_BU);
    float* S1s = (float*)(sb + O_S1);
    float* S2s = (float*)(sb + O_S2);
    float* MSs = (float*)(sb + O_MS);
    float* RSs = (float*)(sb + O_RS);

    for (int i = tid; i < ED; i += NTH) BU[i] = bup[i];
    if (tid < BN) { S1s[tid] = g_S1[tid]; S2s[tid] = g_S2[tid]; }

    float sum = 0.f, sq = 0.f;
    const float* xrow = x + (row0 + cr) * ED;

    // ---- prologue: stage Wd chunk 0 + convert X chunk 0 (both subs) ----
    stage_w128(sa + O_WB(0), g_wdh, 0, tid);
    CP_COMMIT();
    {
        char* xb = sb + O_XB(0);
        #pragma unroll
        for (int sub = 0; sub < 2; ++sub) {
            #pragma unroll
            for (int g = 0; g < 2; ++g) {
                float4 v0 = *(const float4*)(xrow + sub * 64 + cs * 16 + g * 8);
                float4 v1 = *(const float4*)(xrow + sub * 64 + cs * 16 + g * 8 + 4);
                sum += v0.x + v0.y + v0.z + v0.w + v1.x + v1.y + v1.z + v1.w;
                sq  += v0.x*v0.x + v0.y*v0.y + v0.z*v0.z + v0.w*v0.w
                     + v1.x*v1.x + v1.y*v1.y + v1.z*v1.z + v1.w*v1.w;
                *(uint4*)(xb + sub * 8192 + SWB(cr, 2 * cs + g)) =
                    make_uint4(pack_bf(v0.x, v0.y), pack_bf(v0.z, v0.w),
                               pack_bf(v1.x, v1.y), pack_bf(v1.z, v1.w));
            }
        }
    }

    // ================= GEMM1: H[64,64] = X * (gamma*Wd)^T (bf16, 128-wide chunks) =====
    float C1[4][4];
    #pragma unroll
    for (int nt = 0; nt < 4; ++nt)
        #pragma unroll
        for (int i = 0; i < 4; ++i) C1[nt][i] = 0.f;

    for (int c = 0; c < NCH; ++c) {
        CP_WAIT0();
        __syncthreads();
        float4 pf[8];
        if (c < NCH - 1) {
            stage_w128(sa + O_WB((c + 1) & 1), g_wdh, c + 1, tid);
            CP_COMMIT();
            const float* xp = xrow + (c + 1) * 128;
            #pragma unroll
            for (int q = 0; q < 8; ++q)
                pf[q] = *(const float4*)(xp + (q >> 2) * 64 + cs * 16 + (q & 3) * 4);
        }
        const unsigned rowA = m * 16 + (lane & 15);
        #pragma unroll
        for (int sub = 0; sub < 2; ++sub) {
            unsigned xb = sa + O_XB(c & 1) + sub * 8192;
            unsigned wb = sa + O_WB(c & 1) + sub * 8192;
            #pragma unroll
            for (int kp = 0; kp < 2; ++kp) {
                unsigned ah0[4], ah1[4];
                unsigned uA0 = 4 * kp + (lane >> 4), uA1 = uA0 + 2;
                ldsm4(ah0, xb + SWB(rowA, uA0));
                ldsm4(ah1, xb + SWB(rowA, uA1));
                #pragma unroll
                for (int nt = 0; nt < 4; ++nt) {
                    unsigned bh[4];
                    unsigned rowB = nh * 32 + nt * 8 + (lane & 7);
                    unsigned uB = 4 * kp + (lane >> 3);
                    ldsm4(bh, wb + SWB(rowB, uB));
                    mma_bf(C1[nt], ah0, bh);
                    mma_bf(C1[nt], ah1, bh + 2);
                }
            }
        }
        if (c < NCH - 1) {
            char* xcb = sb + O_XB((c + 1) & 1);
            #pragma unroll
            for (int sub = 0; sub < 2; ++sub) {
                #pragma unroll
                for (int g = 0; g < 2; ++g) {
                    float4 v0 = pf[sub * 4 + g * 2], v1 = pf[sub * 4 + g * 2 + 1];
                    sum += v0.x + v0.y + v0.z + v0.w + v1.x + v1.y + v1.z + v1.w;
                    sq  += v0.x*v0.x + v0.y*v0.y + v0.z*v0.z + v0.w*v0.w
                         + v1.x*v1.x + v1.y*v1.y + v1.z*v1.z + v1.w*v1.w;
                    *(uint4*)(xcb + sub * 8192 + SWB(cr, 2 * cs + g)) =
                        make_uint4(pack_bf(v0.x, v0.y), pack_bf(v0.z, v0.w),
                                   pack_bf(v1.x, v1.y), pack_bf(v1.z, v1.w));
                }
            }
        }
    }

    // ---- LN stats: 4 lanes per row -> MS/RS ----
    #pragma unroll
    for (int o = 1; o < 4; o <<= 1) {
        sum += __shfl_xor_sync(0xFFFFFFFFu, sum, o);
        sq  += __shfl_xor_sync(0xFFFFFFFFu, sq,  o);
    }
    if (cs == 0) {
        float mean = sum * (1.f / ED);
        MSs[cr] = mean;
        RSs[cr] = rsqrtf(sq * (1.f / ED) - mean * mean + 1e-5f);
    }
    __syncthreads();

    // ---- LN finalize + GELU directly on C1 frags -> HH (bf16) ----
    {
        int rA_ = m * 16 + (lane >> 2), rB_ = rA_ + 8;
        float meanA = MSs[rA_], rstdA = RSs[rA_];
        float meanB = MSs[rB_], rstdB = RSs[rB_];
        #pragma unroll
        for (int nt = 0; nt < 4; ++nt) {
            int c0 = nh * 32 + nt * 8 + cb;
            float2 s1p = *(const float2*)(S1s + c0);
            float2 s2p = *(const float2*)(S2s + c0);
            float tA0 = rstdA * C1[nt][0] - rstdA * meanA * s1p.x + s2p.x;
            float tA1 = rstdA * C1[nt][1] - rstdA * meanA * s1p.y + s2p.y;
            float tB0 = rstdB * C1[nt][2] - rstdB * meanB * s1p.x + s2p.x;
            float tB1 = rstdB * C1[nt][3] - rstdB * meanB * s1p.y + s2p.y;
            unsigned u = nh * 4 + nt;
            *(unsigned*)(sb + O_HH + SWB(rA_, u) + cb * 2) = pack_bf(gelu_exact(tA0), gelu_exact(tA1));
            *(unsigned*)(sb + O_HH + SWB(rB_, u) + cb * 2) = pack_bf(gelu_exact(tB0), gelu_exact(tB1));
        }
    }
    __syncthreads();

    // ================= GEMM2 (bf16): out = H * Wu^T + b_up + x (128-wide chunks) =====
    // warp grid: 2 m-halves (32 rows) x 4 d-quarters (16 cols per 64-sub)
    const int md = warp & 1;
    const int dq = warp >> 1;
    unsigned Ah[2][4][4];
    {
        #pragma unroll
        for (int mt = 0; mt < 2; ++mt) {
            unsigned rowA_ = md * 32 + mt * 16 + (lane & 15);
            #pragma unroll
            for (int kk = 0; kk < 4; ++kk) {
                unsigned uA = 2 * kk + (lane >> 4);
                ldsm4(Ah[mt][kk], sa + O_HH + SWB(rowA_, uA));
            }
        }
    }
    stage_w128(sa + O_WB(0), g_wuh, 0, tid);
    CP_COMMIT();

    const long rA0 = row0 + md * 32 + (lane >> 2);       // mt=0 rows
    const long rA1 = rA0 + 16;                            // mt=1 rows
    float na[2] = {0.f, 0.f}, nb[2] = {0.f, 0.f};
    for (int c = 0; c < NCH; ++c) {
        CP_WAIT0();
        __syncthreads();
        if (c < NCH - 1) {
            stage_w128(sa + O_WB((c + 1) & 1), g_wuh, c + 1, tid);
            CP_COMMIT();
        }
        #pragma unroll
        for (int sub = 0; sub < 2; ++sub) {
            // residual prefetch: [mt][half][nt]
            float2 fr[2][2][2];
            #pragma unroll
            for (int nt = 0; nt < 2; ++nt) {
                int col = c * 128 + sub * 64 + dq * 16 + nt * 8 + cb;
                fr[0][0][nt] = *(const float2*)(x + rA0 * ED + col);
                fr[0][1][nt] = *(const float2*)(x + (rA0 + 8) * ED + col);
                fr[1][0][nt] = *(const float2*)(x + rA1 * ED + col);
                fr[1][1][nt] = *(const float2*)(x + (rA1 + 8) * ED + col);
            }
            unsigned wb = sa + O_WB(c & 1) + sub * 8192;
            unsigned bh[2][4];
            #pragma unroll
            for (int nt = 0; nt < 2; ++nt) {
                unsigned rowB_ = dq * 16 + nt * 8 + (lane & 7);
                #pragma unroll
                for (int kp = 0; kp < 2; ++kp) {
                    unsigned uB = 4 * kp + (lane >> 3);
                    ldsm4(bh[kp], wb + SWB(rowB_, uB));
                }
                #pragma unroll
                for (int mt = 0; mt < 2; ++mt) {
                    float C2[4] = {0.f, 0.f, 0.f, 0.f};
                    #pragma unroll
                    for (int kk = 0; kk < 4; ++kk)
                        mma_bf(C2, Ah[mt][kk], &bh[kk >> 1][(kk & 1) * 2]);
                    int col = c * 128 + sub * 64 + dq * 16 + nt * 8 + cb;
                    long r0_ = (mt ? rA1 : rA0);
                    float v0 = C2[0] + fr[mt][0][nt].x + BU[col];
                    float v1 = C2[1] + fr[mt][0][nt].y + BU[col + 1];
                    na[mt] += v0 * v0 + v1 * v1;
                    *(float2*)(out + r0_ * ED + col) = make_float2(v0, v1);
                    float v2 = C2[2] + fr[mt][1][nt].x + BU[col];
                    float v3 = C2[3] + fr[mt][1][nt].y + BU[col + 1];
                    nb[mt] += v2 * v2 + v3 * v3;
                    *(float2*)(out + (r0_ + 8) * ED + col) = make_float2(v2, v3);
                }
            }
        }
    }

    // ---- cross-warp row sumsq: 4 dq-warps per row ----
    #pragma unroll
    for (int o = 1; o < 4; o <<= 1) {
        na[0] += __shfl_xor_sync(0xFFFFFFFFu, na[0], o);
        na[1] += __shfl_xor_sync(0xFFFFFFFFu, na[1], o);
        nb[0] += __shfl_xor_sync(0xFFFFFFFFu, nb[0], o);
        nb[1] += __shfl_xor_sync(0xFFFFFFFFu, nb[1], o);
    }
    if ((lane & 3) == 0) {
        float* NR = (float*)(sb + O_NRM);
        int rl = lane >> 2;
        NR[(md * 32 + rl) * 5 + dq]      = na[0];
        NR[(md * 32 + rl + 8) * 5 + dq]  = nb[0];
        NR[(md * 32 + 16 + rl) * 5 + dq] = na[1];
        NR[(md * 32 + 24 + rl) * 5 + dq] = nb[1];
    }
    __syncthreads();
    if (tid < MT) {
        const float* NR = (const float*)(sb + O_NRM) + tid * 5;
        float s = NR[0] + NR[1] + NR[2] + NR[3];
        ((float*)(sb + O_INV))[tid] = 1.f / fmaxf(sqrtf(s), 1e-12f);
    }
    __syncthreads();

    // ---- rescale (L2-hot re-read of this CTA's output) ----
    {
        float sc = ((float*)(sb + O_INV))[cr];
        float4* op = (float4*)(out + (row0 + cr) * ED);
        #pragma unroll 8
        for (int j = 0; j < 96; ++j) {
            float4 v = op[j * 4 + cs];
            v.x *= sc; v.y *= sc; v.z *= sc; v.w *= sc;
            op[j * 4 + cs] = v;
        }
    }
}

extern "C" void kernel_launch(void* const* d_in, const int* in_sizes, int n_in,
                              void* d_out, int out_size) {
    const float* x      = (const float*)d_in[0];
    const float* w_down = (const float*)d_in[1];
    const float* b_down = (const float*)d_in[2];
    const float* w_up   = (const float*)d_in[3];
    const float* b_up   = (const float*)d_in[4];
    const float* gamma  = (const float*)d_in[5];
    const float* beta   = (const float*)d_in[6];
    float* out = (float*)d_out;

    const int n_rows = in_sizes[0] / ED;   // 32768

    cudaFuncSetAttribute(peft_mma, cudaFuncAttributeMaxDynamicSharedMemorySize, SMEM_REQ);

    prep_all<<<88, 256>>>(w_down, b_down, gamma, beta, w_up);
    peft_mma<<<n_rows / MT, NTH, SMEM_REQ>>>(x, b_up, out);
}

// round 13
// speedup vs baseline: 1.0787x; 1.0787x over previous
#include <cuda_runtime.h>
#include <cuda_bf16.h>
#include <math.h>

#define ED 1536
#define BN 64
#define MT 64
#define NTH 256
#define NCH 24

// ---- smem byte offsets (from 1KB-aligned base) ----
#define O_XF(b)  ((b) * 17408)            // raw fp32 x chunk, 64 rows x 272B, double buffer
#define O_XB(b)  (34816 + (b) * 8192)     // X chunk bf16, double buffer
#define O_WB(b)  (51200 + (b) * 8192)     // W chunk bf16, double buffer
#define O_HH     67584                    // H bf16: 64 rows x 128B
#define O_BU     75776
#define O_S1     81920
#define O_S2     82176
#define O_MS     82432
#define O_RS     82688
#define O_NRM    82944                    // 64 x 5 fp32
#define O_INV    84224
#define SMEM_REQ (84480 + 1024)

__device__ __nv_bfloat16 g_wdh[BN * ED];   // [24][64 n][64 k]  (gamma-folded, bf16)
__device__ __nv_bfloat16 g_wuh[ED * BN];   // [24][64 d][64 k]
__device__ float g_S1[BN], g_S2[BN];

// 128B rows, 8 units of 16B, XOR swizzle
__device__ __forceinline__ unsigned SWB(unsigned r, unsigned u) {
    return r * 128 + (((u ^ r) & 7) * 16);
}

__device__ __forceinline__ void ldsm4(unsigned* r, unsigned a) {
    asm volatile("ldmatrix.sync.aligned.m8n8.x4.shared.b16 {%0,%1,%2,%3}, [%4];"
                 : "=r"(r[0]), "=r"(r[1]), "=r"(r[2]), "=r"(r[3]) : "r"(a));
}
__device__ __forceinline__ void mma_bf(float* c, const unsigned* a, const unsigned* b) {
    asm volatile("mma.sync.aligned.m16n8k16.row.col.f32.bf16.bf16.f32 "
                 "{%0,%1,%2,%3},{%4,%5,%6,%7},{%8,%9},{%0,%1,%2,%3};"
                 : "+f"(c[0]), "+f"(c[1]), "+f"(c[2]), "+f"(c[3])
                 : "r"(a[0]), "r"(a[1]), "r"(a[2]), "r"(a[3]), "r"(b[0]), "r"(b[1]));
}
__device__ __forceinline__ void cp16(unsigned dst, const void* src) {
    asm volatile("cp.async.cg.shared.global [%0], [%1], 16;" :: "r"(dst), "l"(src));
}
#define CP_COMMIT() asm volatile("cp.async.commit_group;" ::: "memory")
#define CP_WAIT0()  asm volatile("cp.async.wait_group 0;" ::: "memory")
#define CP_WAIT1()  asm volatile("cp.async.wait_group 1;" ::: "memory")

__device__ __forceinline__ unsigned pack_bf(float a, float b) {
    __nv_bfloat16 ha = __float2bfloat16_rn(a), hb = __float2bfloat16_rn(b);
    return (unsigned)__bfloat16_as_ushort(ha) | ((unsigned)__bfloat16_as_ushort(hb) << 16);
}
__device__ __forceinline__ float gelu_exact(float t) {
    return 0.5f * t * (1.f + erff(t * 0.70710678118654752f));
}

// ---------- merged prep: blocks 0..63 -> w_down row; 64..87 -> w_up chunk ----------
__global__ void prep_all(const float* __restrict__ w_down, const float* __restrict__ b_down,
                         const float* __restrict__ gamma,  const float* __restrict__ beta,
                         const float* __restrict__ w_up) {
    int tid = threadIdx.x;
    if (blockIdx.x < 64) {
        int b = blockIdx.x;
        float s1 = 0.f, s2 = 0.f;
        for (int k = tid; k < ED; k += 256) {
            float w = w_down[b * ED + k];
            float wg = w * gamma[k];
            __nv_bfloat16 hi = __float2bfloat16_rn(wg);
            s1 += __bfloat162float(hi);        // S1 matches the bf16 weights actually used
            s2 += beta[k] * w;
            int idx = (k >> 6) * 4096 + b * 64 + (k & 63);
            g_wdh[idx] = hi;
        }
        __shared__ float r1[256], r2[256];
        r1[tid] = s1; r2[tid] = s2; __syncthreads();
        for (int s = 128; s > 0; s >>= 1) {
            if (tid < s) { r1[tid] += r1[tid + s]; r2[tid] += r2[tid + s]; }
            __syncthreads();
        }
        if (tid == 0) { g_S1[b] = r1[0]; g_S2[b] = r2[0] + b_down[b]; }
    } else {
        int c = blockIdx.x - 64;
        for (int i = tid; i < 4096; i += 256) {
            int d = i >> 6, k = i & 63;
            g_wuh[c * 4096 + i] = __float2bfloat16_rn(w_up[(c * 64 + d) * BN + k]);
        }
    }
}

// stage one 8KB weight chunk (swizzled)
__device__ __forceinline__ void stage_w64(unsigned dst, const __nv_bfloat16* src, int tid) {
    #pragma unroll
    for (int s = 0; s < 2; ++s) {
        int i = tid * 2 + s, n = i >> 3, u = i & 7;
        cp16(dst + SWB(n, u), src + n * 64 + u * 8);
    }
}
// stage one raw fp32 x chunk (64 rows x 256B, padded stride 272B)
__device__ __forceinline__ void stage_xf(unsigned dst, const float* xbase, int tid) {
    #pragma unroll
    for (int s = 0; s < 4; ++s) {
        int i = tid + s * 256;
        int row = i >> 4, seg = i & 15;
        cp16(dst + row * 272 + seg * 16, xbase + (long)row * ED + seg * 4);
    }
}

// ---------- main ----------
__global__ void __launch_bounds__(NTH, 2)
peft_mma(const float* __restrict__ x, const float* __restrict__ bup, float* __restrict__ out) {
    extern __shared__ char smraw[];
    unsigned rawa = (unsigned)__cvta_generic_to_shared(smraw);
    unsigned sa = (rawa + 1023) & ~1023u;
    char* sb = smraw + (sa - rawa);

    const int tid = threadIdx.x, warp = tid >> 5, lane = tid & 31;
    const int m = warp & 3, nh = warp >> 2;   // GEMM1: 4 m-tiles x 2 n-halves
    const long row0 = (long)blockIdx.x * MT;
    const int cr = tid >> 2, cs = tid & 3;    // conversion row / quarter
    const int cb = (lane & 3) * 2;            // col pair base

    float* BU  = (float*)(sb + O_BU);
    float* S1s = (float*)(sb + O_S1);
    float* S2s = (float*)(sb + O_S2);
    float* MSs = (float*)(sb + O_MS);
    float* RSs = (float*)(sb + O_RS);

    const float* xcta = x + row0 * ED;
    float sum = 0.f, sq = 0.f;

    // ---- prologue: async-stage W0+XF0 (group A), XF1 (group B) ----
    stage_w64(sa + O_WB(0), g_wdh, tid);
    stage_xf(sa + O_XF(0), xcta, tid);
    CP_COMMIT();
    stage_xf(sa + O_XF(1), xcta + 64, tid);
    CP_COMMIT();

    for (int i = tid; i < ED; i += NTH) BU[i] = bup[i];
    if (tid < BN) { S1s[tid] = g_S1[tid]; S2s[tid] = g_S2[tid]; }

    CP_WAIT1();
    __syncthreads();
    // convert chunk 0: XF(0) -> XB(0), accumulate stats
    {
        const float* xf = (const float*)(sb + O_XF(0)) + cr * 68 + cs * 16;
        char* xb = sb + O_XB(0);
        #pragma unroll
        for (int g = 0; g < 2; ++g) {
            float4 v0 = *(const float4*)(xf + g * 8);
            float4 v1 = *(const float4*)(xf + g * 8 + 4);
            sum += v0.x + v0.y + v0.z + v0.w + v1.x + v1.y + v1.z + v1.w;
            sq  += v0.x*v0.x + v0.y*v0.y + v0.z*v0.z + v0.w*v0.w
                 + v1.x*v1.x + v1.y*v1.y + v1.z*v1.z + v1.w*v1.w;
            *(uint4*)(xb + SWB(cr, 2 * cs + g)) =
                make_uint4(pack_bf(v0.x, v0.y), pack_bf(v0.z, v0.w),
                           pack_bf(v1.x, v1.y), pack_bf(v1.z, v1.w));
        }
    }

    // ================= GEMM1: H[64,64] = X * (gamma*Wd)^T (bf16) =================
    float C1[4][4];
    #pragma unroll
    for (int nt = 0; nt < 4; ++nt)
        #pragma unroll
        for (int i = 0; i < 4; ++i) C1[nt][i] = 0.f;

    for (int c = 0; c < NCH; ++c) {
        CP_WAIT0();
        __syncthreads();
        if (c + 1 < NCH) {
            stage_w64(sa + O_WB((c + 1) & 1), g_wdh + (c + 1) * 4096, tid);
            if (c + 2 < NCH)
                stage_xf(sa + O_XF(c & 1), xcta + (c + 2) * 64, tid);
            CP_COMMIT();
        }
        unsigned xb = sa + O_XB(c & 1);
        unsigned wb = sa + O_WB(c & 1);
        const unsigned rowA = m * 16 + (lane & 15);
        #pragma unroll
        for (int kp = 0; kp < 2; ++kp) {
            unsigned ah0[4], ah1[4];
            unsigned uA0 = 4 * kp + (lane >> 4), uA1 = uA0 + 2;
            ldsm4(ah0, xb + SWB(rowA, uA0));
            ldsm4(ah1, xb + SWB(rowA, uA1));
            #pragma unroll
            for (int nt = 0; nt < 4; ++nt) {
                unsigned bh[4];
                unsigned rowB = nh * 32 + nt * 8 + (lane & 7);
                unsigned uB = 4 * kp + (lane >> 3);
                ldsm4(bh, wb + SWB(rowB, uB));
                mma_bf(C1[nt], ah0, bh);
                mma_bf(C1[nt], ah1, bh + 2);
            }
        }
        // convert chunk c+1 from XF((c+1)&1) -> XB((c+1)&1)
        if (c + 1 < NCH) {
            const float* xf = (const float*)(sb + O_XF((c + 1) & 1)) + cr * 68 + cs * 16;
            char* xcb = sb + O_XB((c + 1) & 1);
            #pragma unroll
            for (int g = 0; g < 2; ++g) {
                float4 v0 = *(const float4*)(xf + g * 8);
                float4 v1 = *(const float4*)(xf + g * 8 + 4);
                sum += v0.x + v0.y + v0.z + v0.w + v1.x + v1.y + v1.z + v1.w;
                sq  += v0.x*v0.x + v0.y*v0.y + v0.z*v0.z + v0.w*v0.w
                     + v1.x*v1.x + v1.y*v1.y + v1.z*v1.z + v1.w*v1.w;
                *(uint4*)(xcb + SWB(cr, 2 * cs + g)) =
                    make_uint4(pack_bf(v0.x, v0.y), pack_bf(v0.z, v0.w),
                               pack_bf(v1.x, v1.y), pack_bf(v1.z, v1.w));
            }
        }
    }

    // ---- stage GEMM2 group P0 (Wu0 + XR0) — WB buf0 and XF buf0 are dead ----
    stage_w64(sa + O_WB(0), g_wuh, tid);
    stage_xf(sa + O_XF(0), xcta, tid);
    CP_COMMIT();

    // ---- LN stats: 4 lanes per row -> MS/RS ----
    #pragma unroll
    for (int o = 1; o < 4; o <<= 1) {
        sum += __shfl_xor_sync(0xFFFFFFFFu, sum, o);
        sq  += __shfl_xor_sync(0xFFFFFFFFu, sq,  o);
    }
    if (cs == 0) {
        float mean = sum * (1.f / ED);
        MSs[cr] = mean;
        RSs[cr] = rsqrtf(sq * (1.f / ED) - mean * mean + 1e-5f);
    }
    __syncthreads();

    // ---- LN finalize + GELU directly on C1 frags -> HH (bf16) ----
    {
        int rA_ = m * 16 + (lane >> 2), rB_ = rA_ + 8;
        float meanA = MSs[rA_], rstdA = RSs[rA_];
        float meanB = MSs[rB_], rstdB = RSs[rB_];
        #pragma unroll
        for (int nt = 0; nt < 4; ++nt) {
            int c0 = nh * 32 + nt * 8 + cb;
            float2 s1p = *(const float2*)(S1s + c0);
            float2 s2p = *(const float2*)(S2s + c0);
            float tA0 = rstdA * C1[nt][0] - rstdA * meanA * s1p.x + s2p.x;
            float tA1 = rstdA * C1[nt][1] - rstdA * meanA * s1p.y + s2p.y;
            float tB0 = rstdB * C1[nt][2] - rstdB * meanB * s1p.x + s2p.x;
            float tB1 = rstdB * C1[nt][3] - rstdB * meanB * s1p.y + s2p.y;
            unsigned u = nh * 4 + nt;
            *(unsigned*)(sb + O_HH + SWB(rA_, u) + cb * 2) = pack_bf(gelu_exact(tA0), gelu_exact(tA1));
            *(unsigned*)(sb + O_HH + SWB(rB_, u) + cb * 2) = pack_bf(gelu_exact(tB0), gelu_exact(tB1));
        }
    }
    __syncthreads();

    // stage GEMM2 group P1 (Wu1 + XR1) — WB buf1 and XF buf1 dead after sync
    stage_w64(sa + O_WB(1), g_wuh + 4096, tid);
    stage_xf(sa + O_XF(1), xcta + 64, tid);
    CP_COMMIT();

    // ================= GEMM2 (bf16): out = H * Wu^T + b_up + x =================
    // warp grid: 2 m-halves (32 rows) x 4 d-quarters (16 cols per 64-chunk)
    const int md = warp & 1;
    const int dq = warp >> 1;
    unsigned Ah[2][4][4];
    {
        #pragma unroll
        for (int mt = 0; mt < 2; ++mt) {
            unsigned rowA_ = md * 32 + mt * 16 + (lane & 15);
            #pragma unroll
            for (int kk = 0; kk < 4; ++kk) {
                unsigned uA = 2 * kk + (lane >> 4);
                ldsm4(Ah[mt][kk], sa + O_HH + SWB(rowA_, uA));
            }
        }
    }

    const int lrbase = md * 32 + (lane >> 2);
    const long rA0 = row0 + lrbase;
    const long rA1 = rA0 + 16;
    float na[2] = {0.f, 0.f}, nb[2] = {0.f, 0.f};
    for (int c = 0; c < NCH; ++c) {
        if (c >= NCH - 1) { CP_WAIT0(); } else { CP_WAIT1(); }
        __syncthreads();
        unsigned wb = sa + O_WB(c & 1);
        const float* xr = (const float*)(sb + O_XF(c & 1));
        unsigned bh[2][4];
        #pragma unroll
        for (int nt = 0; nt < 2; ++nt) {
            unsigned rowB_ = dq * 16 + nt * 8 + (lane & 7);
            #pragma unroll
            for (int kp = 0; kp < 2; ++kp) {
                unsigned uB = 4 * kp + (lane >> 3);
                ldsm4(bh[kp], wb + SWB(rowB_, uB));
            }
            int colL = dq * 16 + nt * 8 + cb;
            int col = c * 64 + colL;
            #pragma unroll
            for (int mt = 0; mt < 2; ++mt) {
                float C2[4] = {0.f, 0.f, 0.f, 0.f};
                #pragma unroll
                for (int kk = 0; kk < 4; ++kk)
                    mma_bf(C2, Ah[mt][kk], &bh[kk >> 1][(kk & 1) * 2]);
                int lr = lrbase + mt * 16;
                long r0_ = (mt ? rA1 : rA0);
                float2 f0 = *(const float2*)(xr + lr * 68 + colL);
                float2 f1 = *(const float2*)(xr + (lr + 8) * 68 + colL);
                float v0 = C2[0] + f0.x + BU[col];
                float v1 = C2[1] + f0.y + BU[col + 1];
                na[mt] += v0 * v0 + v1 * v1;
                *(float2*)(out + r0_ * ED + col) = make_float2(v0, v1);
                float v2 = C2[2] + f1.x + BU[col];
                float v3 = C2[3] + f1.y + BU[col + 1];
                nb[mt] += v2 * v2 + v3 * v3;
                *(float2*)(out + (r0_ + 8) * ED + col) = make_float2(v2, v3);
            }
        }
        if (c + 2 < NCH) {
            __syncthreads();   // all reads of buffer (c&1) done before overwrite
            stage_w64(sa + O_WB(c & 1), g_wuh + (c + 2) * 4096, tid);
            stage_xf(sa + O_XF(c & 1), xcta + (c + 2) * 64, tid);
            CP_COMMIT();
        }
    }

    // ---- cross-warp row sumsq: 4 dq-warps per row ----
    #pragma unroll
    for (int o = 1; o < 4; o <<= 1) {
        na[0] += __shfl_xor_sync(0xFFFFFFFFu, na[0], o);
        na[1] += __shfl_xor_sync(0xFFFFFFFFu, na[1], o);
        nb[0] += __shfl_xor_sync(0xFFFFFFFFu, nb[0], o);
        nb[1] += __shfl_xor_sync(0xFFFFFFFFu, nb[1], o);
    }
    if ((lane & 3) == 0) {
        float* NR = (float*)(sb + O_NRM);
        int rl = lane >> 2;
        NR[(md * 32 + rl) * 5 + dq]      = na[0];
        NR[(md * 32 + rl + 8) * 5 + dq]  = nb[0];
        NR[(md * 32 + 16 + rl) * 5 + dq] = na[1];
        NR[(md * 32 + 24 + rl) * 5 + dq] = nb[1];
    }
    __syncthreads();
    if (tid < MT) {
        const float* NR = (const float*)(sb + O_NRM) + tid * 5;
        float s = NR[0] + NR[1] + NR[2] + NR[3];
        ((float*)(sb + O_INV))[tid] = 1.f / fmaxf(sqrtf(s), 1e-12f);
    }
    __syncthreads();

    // ---- rescale (L2-hot re-read of this CTA's output) ----
    {
        float sc = ((float*)(sb + O_INV))[cr];
        float4* op = (float4*)(out + (row0 + cr) * ED);
        #pragma unroll 8
        for (int j = 0; j < 96; ++j) {
            float4 v = op[j * 4 + cs];
            v.x *= sc; v.y *= sc; v.z *= sc; v.w *= sc;
            op[j * 4 + cs] = v;
        }
    }
}

extern "C" void kernel_launch(void* const* d_in, const int* in_sizes, int n_in,
                              void* d_out, int out_size) {
    const float* x      = (const float*)d_in[0];
    const float* w_down = (const float*)d_in[1];
    const float* b_down = (const float*)d_in[2];
    const float* w_up   = (const float*)d_in[3];
    const float* b_up   = (const float*)d_in[4];
    const float* gamma  = (const float*)d_in[5];
    const float* beta   = (const float*)d_in[6];
    float* out = (float*)d_out;

    const int n_rows = in_sizes[0] / ED;   // 32768

    cudaFuncSetAttribute(peft_mma, cudaFuncAttributeMaxDynamicSharedMemorySize, SMEM_REQ);

    prep_all<<<88, 256>>>(w_down, b_down, gamma, beta, w_up);
    peft_mma<<<n_rows / MT, NTH, SMEM_REQ>>>(x, b_up, out);
}

// round 16
// speedup vs baseline: 1.0789x; 1.0002x over previous
#include <cuda_runtime.h>
#include <cuda_bf16.h>
#include <math.h>

#define ED 1536
#define BN 64
#define MT 64
#define NTH 256
#define NCH 24

// ---- smem byte offsets (from 1KB-aligned base) ----
#define O_XF(b)  ((b) * 17408)            // raw fp32 x chunk, 64 rows x 272B, TRIPLE buffer
#define O_XB(b)  (52224 + (b) * 8192)     // X chunk bf16, double buffer
#define O_WB(b)  (68608 + (b) * 8192)     // W chunk bf16, TRIPLE buffer
#define O_HH     93184                    // H bf16: 64 rows x 128B
#define O_BU     101376
#define O_S1     107520
#define O_S2     107776
#define O_MS     108032
#define O_RS     108288
#define O_NRM    108544                   // 64 x 5 fp32
#define O_INV    109824
#define SMEM_REQ (110080 + 1024)

__device__ __nv_bfloat16 g_wdh[BN * ED];   // [24][64 n][64 k]  (gamma-folded, bf16)
__device__ __nv_bfloat16 g_wuh[ED * BN];   // [24][64 d][64 k]
__device__ float g_S1[BN], g_S2[BN];

// 128B rows, 8 units of 16B, XOR swizzle
__device__ __forceinline__ unsigned SWB(unsigned r, unsigned u) {
    return r * 128 + (((u ^ r) & 7) * 16);
}

__device__ __forceinline__ void ldsm4(unsigned* r, unsigned a) {
    asm volatile("ldmatrix.sync.aligned.m8n8.x4.shared.b16 {%0,%1,%2,%3}, [%4];"
                 : "=r"(r[0]), "=r"(r[1]), "=r"(r[2]), "=r"(r[3]) : "r"(a));
}
__device__ __forceinline__ void mma_bf(float* c, const unsigned* a, const unsigned* b) {
    asm volatile("mma.sync.aligned.m16n8k16.row.col.f32.bf16.bf16.f32 "
                 "{%0,%1,%2,%3},{%4,%5,%6,%7},{%8,%9},{%0,%1,%2,%3};"
                 : "+f"(c[0]), "+f"(c[1]), "+f"(c[2]), "+f"(c[3])
                 : "r"(a[0]), "r"(a[1]), "r"(a[2]), "r"(a[3]), "r"(b[0]), "r"(b[1]));
}
__device__ __forceinline__ void cp16(unsigned dst, const void* src) {
    asm volatile("cp.async.cg.shared.global [%0], [%1], 16;" :: "r"(dst), "l"(src));
}
#define CP_COMMIT() asm volatile("cp.async.commit_group;" ::: "memory")
#define CP_WAIT(n)  asm volatile("cp.async.wait_group %0;" :: "n"(n) : "memory")

__device__ __forceinline__ unsigned pack_bf(float a, float b) {
    __nv_bfloat16 ha = __float2bfloat16_rn(a), hb = __float2bfloat16_rn(b);
    return (unsigned)__bfloat16_as_ushort(ha) | ((unsigned)__bfloat16_as_ushort(hb) << 16);
}
__device__ __forceinline__ float gelu_exact(float t) {
    return 0.5f * t * (1.f + erff(t * 0.70710678118654752f));
}

// ---------- merged prep: blocks 0..63 -> w_down row; 64..87 -> w_up chunk ----------
__global__ void prep_all(const float* __restrict__ w_down, const float* __restrict__ b_down,
                         const float* __restrict__ gamma,  const float* __restrict__ beta,
                         const float* __restrict__ w_up) {
    int tid = threadIdx.x;
    if (blockIdx.x < 64) {
        int b = blockIdx.x;
        float s1 = 0.f, s2 = 0.f;
        for (int k = tid; k < ED; k += 256) {
            float w = w_down[b * ED + k];
            float wg = w * gamma[k];
            __nv_bfloat16 hi = __float2bfloat16_rn(wg);
            s1 += __bfloat162float(hi);        // S1 matches the bf16 weights actually used
            s2 += beta[k] * w;
            int idx = (k >> 6) * 4096 + b * 64 + (k & 63);
            g_wdh[idx] = hi;
        }
        __shared__ float r1[256], r2[256];
        r1[tid] = s1; r2[tid] = s2; __syncthreads();
        for (int s = 128; s > 0; s >>= 1) {
            if (tid < s) { r1[tid] += r1[tid + s]; r2[tid] += r2[tid + s]; }
            __syncthreads();
        }
        if (tid == 0) { g_S1[b] = r1[0]; g_S2[b] = r2[0] + b_down[b]; }
    } else {
        int c = blockIdx.x - 64;
        for (int i = tid; i < 4096; i += 256) {
            int d = i >> 6, k = i & 63;
            g_wuh[c * 4096 + i] = __float2bfloat16_rn(w_up[(c * 64 + d) * BN + k]);
        }
    }
}

// stage one 8KB weight chunk (swizzled)
__device__ __forceinline__ void stage_w64(unsigned dst, const __nv_bfloat16* src, int tid) {
    #pragma unroll
    for (int s = 0; s < 2; ++s) {
        int i = tid * 2 + s, n = i >> 3, u = i & 7;
        cp16(dst + SWB(n, u), src + n * 64 + u * 8);
    }
}
// stage one raw fp32 x chunk (64 rows x 256B, padded stride 272B)
__device__ __forceinline__ void stage_xf(unsigned dst, const float* xbase, int tid) {
    #pragma unroll
    for (int s = 0; s < 4; ++s) {
        int i = tid + s * 256;
        int row = i >> 4, seg = i & 15;
        cp16(dst + row * 272 + seg * 16, xbase + (long)row * ED + seg * 4);
    }
}

// ---------- main ----------
__global__ void __launch_bounds__(NTH, 2)
peft_mma(const float* __restrict__ x, const float* __restrict__ bup, float* __restrict__ out) {
    extern __shared__ char smraw[];
    unsigned rawa = (unsigned)__cvta_generic_to_shared(smraw);
    unsigned sa = (rawa + 1023) & ~1023u;
    char* sb = smraw + (sa - rawa);

    const int tid = threadIdx.x, warp = tid >> 5, lane = tid & 31;
    const int m = warp & 3, nh = warp >> 2;   // GEMM1: 4 m-tiles x 2 n-halves
    const long row0 = (long)blockIdx.x * MT;
    const int cr = tid >> 2, cs = tid & 3;    // conversion row / quarter
    const int cb = (lane & 3) * 2;            // col pair base

    float* BU  = (float*)(sb + O_BU);
    float* S1s = (float*)(sb + O_S1);
    float* S2s = (float*)(sb + O_S2);
    float* MSs = (float*)(sb + O_MS);
    float* RSs = (float*)(sb + O_RS);

    const float* xcta = x + row0 * ED;
    float sum = 0.f, sq = 0.f;

    // ---- prologue groups: {XF0}, {W0,XF1}, {W1,XF2}  (chunk k -> XF slot k%3, W slot k%3) ----
    stage_xf(sa + O_XF(0), xcta, tid);                CP_COMMIT();
    stage_w64(sa + O_WB(0), g_wdh, tid);
    stage_xf(sa + O_XF(1), xcta + 64, tid);           CP_COMMIT();
    stage_w64(sa + O_WB(1), g_wdh + 4096, tid);
    stage_xf(sa + O_XF(2), xcta + 128, tid);          CP_COMMIT();

    for (int i = tid; i < ED; i += NTH) BU[i] = bup[i];
    if (tid < BN) { S1s[tid] = g_S1[tid]; S2s[tid] = g_S2[tid]; }

    CP_WAIT(2);          // XF0 done (own copies); barrier below makes all threads' visible
    __syncthreads();
    // convert chunk 0: XF(0) -> XB(0), accumulate stats
    {
        const float* xf = (const float*)(sb + O_XF(0)) + cr * 68 + cs * 16;
        char* xb = sb + O_XB(0);
        #pragma unroll
        for (int g = 0; g < 2; ++g) {
            float4 v0 = *(const float4*)(xf + g * 8);
            float4 v1 = *(const float4*)(xf + g * 8 + 4);
            sum += v0.x + v0.y + v0.z + v0.w + v1.x + v1.y + v1.z + v1.w;
            sq  += v0.x*v0.x + v0.y*v0.y + v0.z*v0.z + v0.w*v0.w
                 + v1.x*v1.x + v1.y*v1.y + v1.z*v1.z + v1.w*v1.w;
            *(uint4*)(xb + SWB(cr, 2 * cs + g)) =
                make_uint4(pack_bf(v0.x, v0.y), pack_bf(v0.z, v0.w),
                           pack_bf(v1.x, v1.y), pack_bf(v1.z, v1.w));
        }
    }

    // ================= GEMM1: H[64,64] = X * (gamma*Wd)^T (bf16) =================
    // Phase c invariant: top-of-phase CP_WAIT(1)+barrier guarantees group
    // G_{c-2} = {W(c), XF(c+1)} complete AND visible to all threads, plus XB(c) STS.
    float C1[4][4];
    #pragma unroll
    for (int nt = 0; nt < 4; ++nt)
        #pragma unroll
        for (int i = 0; i < 4; ++i) C1[nt][i] = 0.f;

    for (int c = 0; c < NCH; ++c) {
        CP_WAIT(1);
        __syncthreads();
        // commit exactly ONE group per phase (empty at tail to keep cadence)
        if (c + 2 < NCH) {
            stage_w64(sa + O_WB((c + 2) % 3), g_wdh + (c + 2) * 4096, tid);
            if (c + 3 < NCH)
                stage_xf(sa + O_XF((c + 3) % 3), xcta + (c + 3) * 64, tid);
            CP_COMMIT();
        } else {
            CP_COMMIT();
        }
        unsigned xb = sa + O_XB(c & 1);
        unsigned wb = sa + O_WB(c % 3);
        const unsigned rowA = m * 16 + (lane & 15);
        #pragma unroll
        for (int kp = 0; kp < 2; ++kp) {
            unsigned ah0[4], ah1[4];
            unsigned uA0 = 4 * kp + (lane >> 4), uA1 = uA0 + 2;
            ldsm4(ah0, xb + SWB(rowA, uA0));
            ldsm4(ah1, xb + SWB(rowA, uA1));
            #pragma unroll
            for (int nt = 0; nt < 4; ++nt) {
                unsigned bh[4];
                unsigned rowB = nh * 32 + nt * 8 + (lane & 7);
                unsigned uB = 4 * kp + (lane >> 3);
                ldsm4(bh, wb + SWB(rowB, uB));
                mma_bf(C1[nt], ah0, bh);
                mma_bf(C1[nt], ah1, bh + 2);
            }
        }
        // convert chunk c+1 from XF((c+1)%3) -> XB((c+1)&1)
        // XF(c+1) was guaranteed complete+visible by THIS phase's wait+barrier (no extra wait).
        if (c + 1 < NCH) {
            const float* xf = (const float*)(sb + O_XF((c + 1) % 3)) + cr * 68 + cs * 16;
            char* xcb = sb + O_XB((c + 1) & 1);
            #pragma unroll
            for (int g = 0; g < 2; ++g) {
                float4 v0 = *(const float4*)(xf + g * 8);
                float4 v1 = *(const float4*)(xf + g * 8 + 4);
                sum += v0.x + v0.y + v0.z + v0.w + v1.x + v1.y + v1.z + v1.w;
                sq  += v0.x*v0.x + v0.y*v0.y + v0.z*v0.z + v0.w*v0.w
                     + v1.x*v1.x + v1.y*v1.y + v1.z*v1.z + v1.w*v1.w;
                *(uint4*)(xcb + SWB(cr, 2 * cs + g)) =
                    make_uint4(pack_bf(v0.x, v0.y), pack_bf(v0.z, v0.w),
                               pack_bf(v1.x, v1.y), pack_bf(v1.z, v1.w));
            }
        }
    }

    // ---- stage GEMM2 P0 = {Wu0 + XR0} — WB0/XF0 dead (all warps past final GEMM1 barrier) ----
    stage_w64(sa + O_WB(0), g_wuh, tid);
    stage_xf(sa + O_XF(0), xcta, tid);
    CP_COMMIT();

    // ---- LN stats: 4 lanes per row -> MS/RS ----
    #pragma unroll
    for (int o = 1; o < 4; o <<= 1) {
        sum += __shfl_xor_sync(0xFFFFFFFFu, sum, o);
        sq  += __shfl_xor_sync(0xFFFFFFFFu, sq,  o);
    }
    if (cs == 0) {
        float mean = sum * (1.f / ED);
        MSs[cr] = mean;
        RSs[cr] = rsqrtf(sq * (1.f / ED) - mean * mean + 1e-5f);
    }
    __syncthreads();

    // ---- LN finalize + GELU directly on C1 frags -> HH (bf16) ----
    {
        int rA_ = m * 16 + (lane >> 2), rB_ = rA_ + 8;
        float meanA = MSs[rA_], rstdA = RSs[rA_];
        float meanB = MSs[rB_], rstdB = RSs[rB_];
        #pragma unroll
        for (int nt = 0; nt < 4; ++nt) {
            int c0 = nh * 32 + nt * 8 + cb;
            float2 s1p = *(const float2*)(S1s + c0);
            float2 s2p = *(const float2*)(S2s + c0);
            float tA0 = rstdA * C1[nt][0] - rstdA * meanA * s1p.x + s2p.x;
            float tA1 = rstdA * C1[nt][1] - rstdA * meanA * s1p.y + s2p.y;
            float tB0 = rstdB * C1[nt][2] - rstdB * meanB * s1p.x + s2p.x;
            float tB1 = rstdB * C1[nt][3] - rstdB * meanB * s1p.y + s2p.y;
            unsigned u = nh * 4 + nt;
            *(unsigned*)(sb + O_HH + SWB(rA_, u) + cb * 2) = pack_bf(gelu_exact(tA0), gelu_exact(tA1));
            *(unsigned*)(sb + O_HH + SWB(rB_, u) + cb * 2) = pack_bf(gelu_exact(tB0), gelu_exact(tB1));
        }
    }

    // stage GEMM2 P1 = {Wu1 + XR1}
    stage_w64(sa + O_WB(1), g_wuh + 4096, tid);
    stage_xf(sa + O_XF(1), xcta + 64, tid);
    CP_COMMIT();
    __syncthreads();     // HH visible for Ah ldsm

    // ================= GEMM2 (bf16): out = H * Wu^T + b_up + x =================
    // warp grid: 2 m-halves (32 rows) x 4 d-quarters (16 cols per 64-chunk)
    const int md = warp & 1;
    const int dq = warp >> 1;
    unsigned Ah[2][4][4];
    {
        #pragma unroll
        for (int mt = 0; mt < 2; ++mt) {
            unsigned rowA_ = md * 32 + mt * 16 + (lane & 15);
            #pragma unroll
            for (int kk = 0; kk < 4; ++kk) {
                unsigned uA = 2 * kk + (lane >> 4);
                ldsm4(Ah[mt][kk], sa + O_HH + SWB(rowA_, uA));
            }
        }
    }

    const int lrbase = md * 32 + (lane >> 2);
    const long rA0 = row0 + lrbase;
    const long rA1 = rA0 + 16;
    float na[2] = {0.f, 0.f}, nb[2] = {0.f, 0.f};
    for (int c = 0; c < NCH; ++c) {
        CP_WAIT(1);          // P(c) done per-thread (P(c+1) may pend)
        __syncthreads();     // cross-thread visibility; buffer (c+2)%3 provably dead
        if (c + 2 < NCH) {
            stage_w64(sa + O_WB((c + 2) % 3), g_wuh + (c + 2) * 4096, tid);
            stage_xf(sa + O_XF((c + 2) % 3), xcta + (c + 2) * 64, tid);
            CP_COMMIT();
        } else {
            CP_COMMIT();     // empty group: tail drain fix
        }
        unsigned wb = sa + O_WB(c % 3);
        const float* xr = (const float*)(sb + O_XF(c % 3));
        unsigned bh[2][4];
        #pragma unroll
        for (int nt = 0; nt < 2; ++nt) {
            unsigned rowB_ = dq * 16 + nt * 8 + (lane & 7);
            #pragma unroll
            for (int kp = 0; kp < 2; ++kp) {
                unsigned uB = 4 * kp + (lane >> 3);
                ldsm4(bh[kp], wb + SWB(rowB_, uB));
            }
            int colL = dq * 16 + nt * 8 + cb;
            int col = c * 64 + colL;
            #pragma unroll
            for (int mt = 0; mt < 2; ++mt) {
                float C2[4] = {0.f, 0.f, 0.f, 0.f};
                #pragma unroll
                for (int kk = 0; kk < 4; ++kk)
                    mma_bf(C2, Ah[mt][kk], &bh[kk >> 1][(kk & 1) * 2]);
                int lr = lrbase + mt * 16;
                long r0_ = (mt ? rA1 : rA0);
                float2 f0 = *(const float2*)(xr + lr * 68 + colL);
                float2 f1 = *(const float2*)(xr + (lr + 8) * 68 + colL);
                float v0 = C2[0] + f0.x + BU[col];
                float v1 = C2[1] + f0.y + BU[col + 1];
                na[mt] += v0 * v0 + v1 * v1;
                *(float2*)(out + r0_ * ED + col) = make_float2(v0, v1);
                float v2 = C2[2] + f1.x + BU[col];
                float v3 = C2[3] + f1.y + BU[col + 1];
                nb[mt] += v2 * v2 + v3 * v3;
                *(float2*)(out + (r0_ + 8) * ED + col) = make_float2(v2, v3);
            }
        }
    }

    // ---- cross-warp row sumsq: 4 dq-warps per row ----
    #pragma unroll
    for (int o = 1; o < 4; o <<= 1) {
        na[0] += __shfl_xor_sync(0xFFFFFFFFu, na[0], o);
        na[1] += __shfl_xor_sync(0xFFFFFFFFu, na[1], o);
        nb[0] += __shfl_xor_sync(0xFFFFFFFFu, nb[0], o);
        nb[1] += __shfl_xor_sync(0xFFFFFFFFu, nb[1], o);
    }
    if ((lane & 3) == 0) {
        float* NR = (float*)(sb + O_NRM);
        int rl = lane >> 2;
        NR[(md * 32 + rl) * 5 + dq]      = na[0];
        NR[(md * 32 + rl + 8) * 5 + dq]  = nb[0];
        NR[(md * 32 + 16 + rl) * 5 + dq] = na[1];
        NR[(md * 32 + 24 + rl) * 5 + dq] = nb[1];
    }
    __syncthreads();
    if (tid < MT) {
        const float* NR = (const float*)(sb + O_NRM) + tid * 5;
        float s = NR[0] + NR[1] + NR[2] + NR[3];
        ((float*)(sb + O_INV))[tid] = 1.f / fmaxf(sqrtf(s), 1e-12f);
    }
    __syncthreads();

    // ---- rescale (L2-hot re-read of this CTA's output) ----
    {
        float sc = ((float*)(sb + O_INV))[cr];
        float4* op = (float4*)(out + (row0 + cr) * ED);
        #pragma unroll 8
        for (int j = 0; j < 96; ++j) {
            float4 v = op[j * 4 + cs];
            v.x *= sc; v.y *= sc; v.z *= sc; v.w *= sc;
            op[j * 4 + cs] = v;
        }
    }
}

extern "C" void kernel_launch(void* const* d_in, const int* in_sizes, int n_in,
                              void* d_out, int out_size) {
    const float* x      = (const float*)d_in[0];
    const float* w_down = (const float*)d_in[1];
    const float* b_down = (const float*)d_in[2];
    const float* w_up   = (const float*)d_in[3];
    const float* b_up   = (const float*)d_in[4];
    const float* gamma  = (const float*)d_in[5];
    const float* beta   = (const float*)d_in[6];
    float* out = (float*)d_out;

    const int n_rows = in_sizes[0] / ED;   // 32768

    cudaFuncSetAttribute(peft_mma, cudaFuncAttributeMaxDynamicSharedMemorySize, SMEM_REQ);

    prep_all<<<88, 256>>>(w_down, b_down, gamma, beta, w_up);
    peft_mma<<<n_rows / MT, NTH, SMEM_REQ>>>(x, b_up, out);
}